// round 15
// baseline (speedup 1.0000x reference)
#include <cuda_runtime.h>
#include <math.h>
#include <stdint.h>

// Problem constants
#define NN      1024
#define DF      6
#define TT      60
#define HH      64
#define GG      192      // 3*H
#define RR      64
#define W2      72       // weight row stride (words), kh-swizzled
#define H2      68       // h row stride (words), kh-swizzled
#define NEG_VAL (-10000.0f)
#define SLOPE   0.01f

// Inter-kernel scratch
__device__ float g_h1[NN * HH];
__device__ float g_sa[NN];
__device__ float g_sb[NN];
__device__ float g_dot[NN * NN];
__device__ float g_sum[NN * NN];

typedef unsigned long long u64;

__device__ __forceinline__ u64 ffma2(u64 a, u64 b, u64 c) {
    u64 d;
    asm("fma.rn.f32x2 %0, %1, %2, %3;" : "=l"(d) : "l"(a), "l"(b), "l"(c));
    return d;
}
__device__ __forceinline__ u64 add2(u64 a, u64 b) {
    u64 d;
    asm("add.rn.f32x2 %0, %1, %2;" : "=l"(d) : "l"(a), "l"(b));
    return d;
}
__device__ __forceinline__ float hsum2(u64 v) {
    float lo, hi;
    asm("mov.b64 {%0,%1}, %2;" : "=f"(lo), "=f"(hi) : "l"(v));
    return lo + hi;
}
__device__ __forceinline__ float tanh_fast(float x) {
    float y;
    asm("tanh.approx.f32 %0, %1;" : "=f"(y) : "f"(x));
    return y;
}
__device__ __forceinline__ float sig_fast(float x) {
    return 0.5f * tanh_fast(0.5f * x) + 0.5f;
}

// Split-K pair reduction (partner = lane^1).
#define RED2(v0, v1, v2, v3, s0, s1)                                          \
    {                                                                         \
        float _ta = __shfl_xor_sync(0xffffffffu, kh ? (v0) : (v2), 1);        \
        float _tb = __shfl_xor_sync(0xffffffffu, kh ? (v1) : (v3), 1);        \
        (s0) = (kh ? (v2) : (v0)) + _ta;                                      \
        (s1) = (kh ? (v3) : (v1)) + _tb;                                      \
    }

// One fused-reldot round: 8 pairs per warp; 4 lanes per pair, 64B per lane.
// qv = lane&3 selects the 64B quarter; leader lane (qv==0) stores results.
__device__ __forceinline__ void rd_round(const float* __restrict__ rel,
                                         const float* __restrict__ sWvR,
                                         size_t p, int qv, int lane)
{
    const ulonglong2* rp =
        (const ulonglong2*)(rel + p * RR + (size_t)qv * 16);
    u64 dacc = 0, sacc = 0;
    #pragma unroll
    for (int i = 0; i < 4; i++) {
        ulonglong2 dv = rp[i];                                   // 16B data
        ulonglong2 wv = *(const ulonglong2*)&sWvR[qv * 16 + i * 4];
        dacc = ffma2(dv.x, wv.x, dacc);
        dacc = ffma2(dv.y, wv.y, dacc);
        sacc = add2(dv.x, sacc);
        sacc = add2(dv.y, sacc);
    }
    float dot  = hsum2(dacc);
    float ssum = hsum2(sacc);
    dot  += __shfl_xor_sync(0xffffffffu, dot, 1);
    ssum += __shfl_xor_sync(0xffffffffu, ssum, 1);
    dot  += __shfl_xor_sync(0xffffffffu, dot, 2);
    ssum += __shfl_xor_sync(0xffffffffu, ssum, 2);
    if ((lane & 3) == 0) {
        g_dot[p] = dot;
        g_sum[p] = ssum;
    }
}

// ---------------------------------------------------------------------------
// Kernel 1: fused 2-layer GRU (R11 merged-GEMM) + interleaved reldot.
// 128 blocks x 8 rows, 256 threads. Per step each warp also computes 16
// relation-dot pairs using idle issue slots + idle DRAM.
// ---------------------------------------------------------------------------
#define GRU_THREADS 256
#define GRU_ROWS    8
#define PAIRS_PER_BLOCK (NN * NN / 128)   // 8192
#define PAIRS_PER_WARP  (PAIRS_PER_BLOCK / 8)  // 1024

__global__ void __launch_bounds__(GRU_THREADS, 1)
gru_kernel(const float* __restrict__ x,
           const float* __restrict__ rel,
           const float* __restrict__ Wih0, const float* __restrict__ Whh0,
           const float* __restrict__ bih0, const float* __restrict__ bhh0,
           const float* __restrict__ Wih1, const float* __restrict__ Whh1,
           const float* __restrict__ bih1, const float* __restrict__ bhh1,
           const float* __restrict__ Wv)
{
    extern __shared__ float smem[];
    float* sWhh0 = smem;                          // 192*72
    float* sWih1 = sWhh0 + GG * W2;               // 192*72
    float* sWhh1 = sWih1 + GG * W2;               // 192*72
    float* sWih0 = sWhh1 + GG * W2;               // 192*8
    float* sX    = sWih0 + GG * 8;                // 8*360
    float* sXt   = sX + GRU_ROWS * 360;           // 2*64
    float* sH0   = sXt + 2 * 64;                  // 2*8*68
    float* sH1   = sH0 + 2 * GRU_ROWS * H2;       // 2*8*68
    float* sWvR  = sH1 + 2 * GRU_ROWS * H2;       // 64 (relation weights)

    const int tid = threadIdx.x;
    const int r0  = blockIdx.x * GRU_ROWS;

    for (int i = tid; i < GG * HH; i += GRU_THREADS) {
        int o = i >> 6, k = i & 63;
        int w = o * W2 + k + ((k >= 32) ? 4 : 0);
        sWhh0[w] = Whh0[i];
        sWih1[w] = Wih1[i];
        sWhh1[w] = Whh1[i];
    }
    for (int i = tid; i < GG * DF; i += GRU_THREADS) {
        int o = i / DF, d = i % DF;
        sWih0[o * 8 + d] = Wih0[i];
    }
    for (int i = tid; i < GRU_ROWS * 360; i += GRU_THREADS) {
        int r = i / 360, cc = i % 360;
        sX[i] = x[(size_t)(r0 + r) * 360 + cc];
    }
    for (int i = tid; i < 2 * GRU_ROWS * H2; i += GRU_THREADS) {
        sH0[i] = 0.f; sH1[i] = 0.f;
    }
    if (tid < GRU_ROWS * DF) {
        int r = tid / DF, d = tid % DF;
        sXt[r * 8 + d] = sX[r * 360 + d * TT + 0];
    }
    if (tid < RR) sWvR[tid] = Wv[2 * HH + tid];

    const int lane  = tid & 31;
    const int warp  = tid >> 5;
    const int kh    = lane & 1;
    const int rg    = (lane >> 1) & 1;
    const int cl    = lane >> 2;
    const int c     = warp * 8 + cl;
    const int rbase = rg * 4;
    const int R0    = rbase + 2 * kh;
    const int wob   = 36 * kh;
    const int swc   = (c >= 32) ? 4 : 0;

    // fused-reldot mapping
    const int    qv    = lane & 3;
    const int    lg    = lane >> 2;          // pair subgroup 0..7
    const size_t pbase = (size_t)blockIdx.x * PAIRS_PER_BLOCK
                       + (size_t)warp * PAIRS_PER_WARP;

    const float br0  = bih0[c] + bhh0[c];
    const float bz0  = bih0[64 + c] + bhh0[64 + c];
    const float bxn0 = bih0[128 + c];
    const float bhn0 = bhh0[128 + c];
    const float br1  = bih1[c] + bhh1[c];
    const float bz1  = bih1[64 + c] + bhh1[64 + c];
    const float bxn1 = bih1[128 + c];
    const float bhn1 = bhh1[128 + c];
    __syncthreads();

    // ---- it = 0 (slot 0 of fused reldot) ----
    {
        #pragma unroll
        for (int rr = 0; rr < 2; rr++) {
            int R = R0 + rr;
            float xr = 0.f, xz = 0.f, xn = 0.f;
            #pragma unroll
            for (int d = 0; d < DF; d++) {
                float xv = sXt[R * 8 + d];
                xr += xv * sWih0[c * 8 + d];
                xz += xv * sWih0[(64 + c) * 8 + d];
                xn += xv * sWih0[(128 + c) * 8 + d];
            }
            float rv = sig_fast(xr + br0);
            float zv = sig_fast(xz + bz0);
            float nv = tanh_fast(xn + bxn0 + rv * bhn0);
            sH0[1 * (GRU_ROWS * H2) + R * H2 + c + swc] = (1.f - zv) * nv;
        }
        rd_round(rel, sWvR, pbase + 0 + lg, qv, lane);
        rd_round(rel, sWvR, pbase + 8 + lg, qv, lane);
        if (tid < GRU_ROWS * DF) {
            int r = tid / DF, d = tid % DF;
            sXt[64 + r * 8 + d] = sX[r * 360 + d * TT + 1];
        }
    }
    __syncthreads();

    // ---- main loop ----
    for (int it = 1; it < TT; ++it) {
        const int pc = it & 1, pn = pc ^ 1;
        float* H0c = sH0 + pc * (GRU_ROWS * H2);
        float* H0n = sH0 + pn * (GRU_ROWS * H2);
        float* H1c = sH1 + pc * (GRU_ROWS * H2);
        float* H1n = sH1 + pn * (GRU_ROWS * H2);

        u64 Ar[4], Az[4], An[4], Br[4], Bz[4], Bxn[4], Bhn[4];
        #pragma unroll
        for (int i = 0; i < 4; i++) {
            Ar[i] = 0; Az[i] = 0; An[i] = 0;
            Br[i] = 0; Bz[i] = 0; Bxn[i] = 0; Bhn[i] = 0;
        }

        #pragma unroll
        for (int q = 0; q < 8; q++) {
            const int wo = wob + q * 4;
            ulonglong2 ar = *(const ulonglong2*)&sWhh0[c * W2 + wo];
            ulonglong2 az = *(const ulonglong2*)&sWhh0[(64 + c) * W2 + wo];
            ulonglong2 an = *(const ulonglong2*)&sWhh0[(128 + c) * W2 + wo];
            ulonglong2 ur = *(const ulonglong2*)&sWih1[c * W2 + wo];
            ulonglong2 uz = *(const ulonglong2*)&sWih1[(64 + c) * W2 + wo];
            ulonglong2 un = *(const ulonglong2*)&sWih1[(128 + c) * W2 + wo];
            ulonglong2 vr = *(const ulonglong2*)&sWhh1[c * W2 + wo];
            ulonglong2 vz = *(const ulonglong2*)&sWhh1[(64 + c) * W2 + wo];
            ulonglong2 vn = *(const ulonglong2*)&sWhh1[(128 + c) * W2 + wo];
            #pragma unroll
            for (int i = 0; i < 4; i++) {
                ulonglong2 h0v = *(const ulonglong2*)&H0c[(rbase + i) * H2 + wo];
                ulonglong2 h1v = *(const ulonglong2*)&H1c[(rbase + i) * H2 + wo];
                Ar[i]  = ffma2(h0v.x, ar.x, Ar[i]);
                Az[i]  = ffma2(h0v.x, az.x, Az[i]);
                An[i]  = ffma2(h0v.x, an.x, An[i]);
                Br[i]  = ffma2(h0v.x, ur.x, Br[i]);
                Bz[i]  = ffma2(h0v.x, uz.x, Bz[i]);
                Bxn[i] = ffma2(h0v.x, un.x, Bxn[i]);
                Br[i]  = ffma2(h1v.x, vr.x, Br[i]);
                Bz[i]  = ffma2(h1v.x, vz.x, Bz[i]);
                Bhn[i] = ffma2(h1v.x, vn.x, Bhn[i]);
                Ar[i]  = ffma2(h0v.y, ar.y, Ar[i]);
                Az[i]  = ffma2(h0v.y, az.y, Az[i]);
                An[i]  = ffma2(h0v.y, an.y, An[i]);
                Br[i]  = ffma2(h0v.y, ur.y, Br[i]);
                Bz[i]  = ffma2(h0v.y, uz.y, Bz[i]);
                Bxn[i] = ffma2(h0v.y, un.y, Bxn[i]);
                Br[i]  = ffma2(h1v.y, vr.y, Br[i]);
                Bz[i]  = ffma2(h1v.y, vz.y, Bz[i]);
                Bhn[i] = ffma2(h1v.y, vn.y, Bhn[i]);
            }
        }

        float sAr[2], sAz[2], sAn[2], sBr[2], sBz[2], sBxn[2], sBhn[2];
        {
            float v0, v1, v2, v3;
            v0 = hsum2(Ar[0]);  v1 = hsum2(Ar[1]);  v2 = hsum2(Ar[2]);  v3 = hsum2(Ar[3]);
            RED2(v0, v1, v2, v3, sAr[0], sAr[1]);
            v0 = hsum2(Az[0]);  v1 = hsum2(Az[1]);  v2 = hsum2(Az[2]);  v3 = hsum2(Az[3]);
            RED2(v0, v1, v2, v3, sAz[0], sAz[1]);
            v0 = hsum2(An[0]);  v1 = hsum2(An[1]);  v2 = hsum2(An[2]);  v3 = hsum2(An[3]);
            RED2(v0, v1, v2, v3, sAn[0], sAn[1]);
            v0 = hsum2(Br[0]);  v1 = hsum2(Br[1]);  v2 = hsum2(Br[2]);  v3 = hsum2(Br[3]);
            RED2(v0, v1, v2, v3, sBr[0], sBr[1]);
            v0 = hsum2(Bz[0]);  v1 = hsum2(Bz[1]);  v2 = hsum2(Bz[2]);  v3 = hsum2(Bz[3]);
            RED2(v0, v1, v2, v3, sBz[0], sBz[1]);
            v0 = hsum2(Bxn[0]); v1 = hsum2(Bxn[1]); v2 = hsum2(Bxn[2]); v3 = hsum2(Bxn[3]);
            RED2(v0, v1, v2, v3, sBxn[0], sBxn[1]);
            v0 = hsum2(Bhn[0]); v1 = hsum2(Bhn[1]); v2 = hsum2(Bhn[2]); v3 = hsum2(Bhn[3]);
            RED2(v0, v1, v2, v3, sBhn[0], sBhn[1]);
        }

        #pragma unroll
        for (int rr = 0; rr < 2; rr++) {
            int R = R0 + rr;
            float xr = 0.f, xz = 0.f, xn = 0.f;
            #pragma unroll
            for (int d = 0; d < DF; d++) {
                float xv = sXt[pc * 64 + R * 8 + d];
                xr += xv * sWih0[c * 8 + d];
                xz += xv * sWih0[(64 + c) * 8 + d];
                xn += xv * sWih0[(128 + c) * 8 + d];
            }
            float rv = sig_fast(xr + sAr[rr] + br0);
            float zv = sig_fast(xz + sAz[rr] + bz0);
            float nv = tanh_fast(xn + bxn0 + rv * (sAn[rr] + bhn0));
            float h0old = H0c[R * H2 + c + swc];
            H0n[R * H2 + c + swc] = (1.f - zv) * nv + zv * h0old;

            float rv1 = sig_fast(sBr[rr] + br1);
            float zv1 = sig_fast(sBz[rr] + bz1);
            float nv1 = tanh_fast(sBxn[rr] + bxn1 + rv1 * (sBhn[rr] + bhn1));
            float h1old = H1c[R * H2 + c + swc];
            H1n[R * H2 + c + swc] = (1.f - zv1) * nv1 + zv1 * h1old;
        }

        // fused reldot: slot `it` (fills issue bubbles + idle DRAM)
        {
            size_t ps = pbase + (size_t)it * 16 + lg;
            rd_round(rel, sWvR, ps, qv, lane);
            rd_round(rel, sWvR, ps + 8, qv, lane);
        }

        if (it + 1 < TT && tid < GRU_ROWS * DF) {
            int r = tid / DF, d = tid % DF;
            sXt[pn * 64 + r * 8 + d] = sX[r * 360 + d * TT + (it + 1)];
        }
        __syncthreads();
    }

    // ---- epilogue: final L1 step -> h1[TT] ----
    {
        float* H0c = sH0 + ((TT) & 1) * (GRU_ROWS * H2);
        float* H1c = sH1 + ((TT) & 1) * (GRU_ROWS * H2);
        float* H1f = sH1 + (((TT) & 1) ^ 1) * (GRU_ROWS * H2);

        u64 Br[4], Bz[4], Bxn[4], Bhn[4];
        #pragma unroll
        for (int i = 0; i < 4; i++) { Br[i] = 0; Bz[i] = 0; Bxn[i] = 0; Bhn[i] = 0; }

        #pragma unroll
        for (int q = 0; q < 8; q++) {
            const int wo = wob + q * 4;
            ulonglong2 ur = *(const ulonglong2*)&sWih1[c * W2 + wo];
            ulonglong2 uz = *(const ulonglong2*)&sWih1[(64 + c) * W2 + wo];
            ulonglong2 un = *(const ulonglong2*)&sWih1[(128 + c) * W2 + wo];
            ulonglong2 vr = *(const ulonglong2*)&sWhh1[c * W2 + wo];
            ulonglong2 vz = *(const ulonglong2*)&sWhh1[(64 + c) * W2 + wo];
            ulonglong2 vn = *(const ulonglong2*)&sWhh1[(128 + c) * W2 + wo];
            #pragma unroll
            for (int i = 0; i < 4; i++) {
                ulonglong2 h0v = *(const ulonglong2*)&H0c[(rbase + i) * H2 + wo];
                ulonglong2 h1v = *(const ulonglong2*)&H1c[(rbase + i) * H2 + wo];
                Br[i]  = ffma2(h0v.x, ur.x, Br[i]);
                Bz[i]  = ffma2(h0v.x, uz.x, Bz[i]);
                Bxn[i] = ffma2(h0v.x, un.x, Bxn[i]);
                Br[i]  = ffma2(h1v.x, vr.x, Br[i]);
                Bz[i]  = ffma2(h1v.x, vz.x, Bz[i]);
                Bhn[i] = ffma2(h1v.x, vn.x, Bhn[i]);
                Br[i]  = ffma2(h0v.y, ur.y, Br[i]);
                Bz[i]  = ffma2(h0v.y, uz.y, Bz[i]);
                Bxn[i] = ffma2(h0v.y, un.y, Bxn[i]);
                Br[i]  = ffma2(h1v.y, vr.y, Br[i]);
                Bz[i]  = ffma2(h1v.y, vz.y, Bz[i]);
                Bhn[i] = ffma2(h1v.y, vn.y, Bhn[i]);
            }
        }
        float sBr[2], sBz[2], sBxn[2], sBhn[2];
        {
            float v0, v1, v2, v3;
            v0 = hsum2(Br[0]);  v1 = hsum2(Br[1]);  v2 = hsum2(Br[2]);  v3 = hsum2(Br[3]);
            RED2(v0, v1, v2, v3, sBr[0], sBr[1]);
            v0 = hsum2(Bz[0]);  v1 = hsum2(Bz[1]);  v2 = hsum2(Bz[2]);  v3 = hsum2(Bz[3]);
            RED2(v0, v1, v2, v3, sBz[0], sBz[1]);
            v0 = hsum2(Bxn[0]); v1 = hsum2(Bxn[1]); v2 = hsum2(Bxn[2]); v3 = hsum2(Bxn[3]);
            RED2(v0, v1, v2, v3, sBxn[0], sBxn[1]);
            v0 = hsum2(Bhn[0]); v1 = hsum2(Bhn[1]); v2 = hsum2(Bhn[2]); v3 = hsum2(Bhn[3]);
            RED2(v0, v1, v2, v3, sBhn[0], sBhn[1]);
        }
        #pragma unroll
        for (int rr = 0; rr < 2; rr++) {
            int R = R0 + rr;
            float rv1 = sig_fast(sBr[rr] + br1);
            float zv1 = sig_fast(sBz[rr] + bz1);
            float nv1 = tanh_fast(sBxn[rr] + bxn1 + rv1 * (sBhn[rr] + bhn1));
            float h1old = H1c[R * H2 + c + swc];
            H1f[R * H2 + c + swc] = (1.f - zv1) * nv1 + zv1 * h1old;
        }
    }

    // fused reldot: remaining 64 pairs per warp (8 rounds)
    #pragma unroll
    for (int rquad = 0; rquad < 8; rquad++)
        rd_round(rel, sWvR, pbase + (size_t)TT * 16 + rquad * 8 + lg, qv, lane);

    __syncthreads();

    // ---- outputs (unswizzle) ----
    const float* hf = sH1 + (((TT) & 1) ^ 1) * (GRU_ROWS * H2);
    for (int i = tid; i < GRU_ROWS * HH; i += GRU_THREADS) {
        int r = i >> 6, cc = i & 63;
        g_h1[(size_t)r0 * HH + i] = hf[r * H2 + cc + ((cc >= 32) ? 4 : 0)];
    }
    if (tid < GRU_ROWS) {
        float a = 0.f, b2s = 0.f;
        #pragma unroll
        for (int cc = 0; cc < HH; cc++) {
            float h = hf[tid * H2 + cc + ((cc >= 32) ? 4 : 0)];
            a   += h * Wv[cc];
            b2s += h * Wv[HH + cc];
        }
        g_sa[r0 + tid] = a;
        g_sb[r0 + tid] = b2s;
    }
}

// ---------------------------------------------------------------------------
// Kernel 2: softmax + agg + FC v4 — vectorized agg (unchanged from R14).
// ---------------------------------------------------------------------------
#define A4_THREADS 512
#define TLD 72

__global__ void __launch_bounds__(A4_THREADS)
att4_kernel(const float* __restrict__ bsc,
            const float* __restrict__ fc_w,
            const float* __restrict__ fc_b,
            float* __restrict__ out)
{
    __shared__ float sP[8 * NN];
    __shared__ float sT[64 * TLD];
    __shared__ float sWmax[16];
    __shared__ float sWsum[16];
    __shared__ float sDen[8];
    __shared__ float sRed[16];

    const int tid  = threadIdx.x;
    const int wid  = tid >> 5;
    const int lane = tid & 31;
    const int i0   = blockIdx.x * 8;

    const int r    = wid >> 1;
    const int part = ((wid & 1) << 5) + lane;
    const int i    = i0 + r;
    const float sa_i = g_sa[i];
    const float bval = bsc[0];

    float tv[16];
    float mx = -INFINITY;
    #pragma unroll
    for (int q4 = 0; q4 < 4; q4++) {
        int j = part * 16 + q4 * 4;
        float4 d4 = *(const float4*)&g_dot[(size_t)i * NN + j];
        float4 s4 = *(const float4*)&g_sum[(size_t)i * NN + j];
        #pragma unroll
        for (int e = 0; e < 4; e++) {
            float dot  = (&d4.x)[e];
            float ssum = (&s4.x)[e];
            float w = sa_i + g_sb[j + e] + dot + bval;
            w = (w >= 0.f) ? w : SLOPE * w;
            float m  = (ssum != 0.f) ? 1.f : 0.f;
            float t  = m * w;
            if (t == 0.f) t = NEG_VAL;
            tv[q4 * 4 + e] = t;
            sP[r * NN + j + e] = m;
            mx = fmaxf(mx, t);
        }
    }
    #pragma unroll
    for (int off = 16; off; off >>= 1) mx = fmaxf(mx, __shfl_xor_sync(0xffffffffu, mx, off));
    if (lane == 0) sWmax[wid] = mx;
    __syncthreads();
    mx = fmaxf(sWmax[r * 2], sWmax[r * 2 + 1]);

    float lsum = 0.f;
    #pragma unroll
    for (int q = 0; q < 16; q++) {
        int j = part * 16 + q;
        float e = __expf(tv[q] - mx);
        lsum += e;
        sP[r * NN + j] = e * sP[r * NN + j];
    }
    #pragma unroll
    for (int off = 16; off; off >>= 1) lsum += __shfl_xor_sync(0xffffffffu, lsum, off);
    if (lane == 0) sWsum[wid] = lsum;
    __syncthreads();
    if (tid < 8) sDen[tid] = sWsum[tid * 2] + sWsum[tid * 2 + 1];
    __syncthreads();

    const int js  = tid & 3;
    const int cg  = (tid >> 2) & 15;
    const int rr2 = tid >> 6;

    u64 a0 = 0, a1 = 0;
    for (int tile = 0; tile < 16; tile++) {
        #pragma unroll
        for (int k = 0; k < 2; k++) {
            int f = tid + k * A4_THREADS;
            float4 v = *(const float4*)&g_h1[(size_t)tile * 4096 + (size_t)f * 4];
            *(float4*)&sT[(f >> 4) * TLD + (f & 15) * 4] = v;
        }
        __syncthreads();
        const float* pr = &sP[rr2 * NN + tile * 64];
        #pragma unroll
        for (int jj = 0; jj < 16; jj++) {
            int jl = jj * 4 + js;
            float p = pr[jl];
            u64 pp;
            asm("mov.b64 %0, {%1, %1};" : "=l"(pp) : "f"(p));
            ulonglong2 tvv = *(const ulonglong2*)&sT[jl * TLD + cg * 4];
            a0 = ffma2(pp, tvv.x, a0);
            a1 = ffma2(pp, tvv.y, a1);
        }
        __syncthreads();
    }

    float acc;
    {
        float v0, v1, v2, v3;
        asm("mov.b64 {%0,%1}, %2;" : "=f"(v0), "=f"(v1) : "l"(a0));
        asm("mov.b64 {%0,%1}, %2;" : "=f"(v2), "=f"(v3) : "l"(a1));
        const bool hiA = (js & 1);
        const bool hiB = ((js >> 1) & 1);
        float t0 = __shfl_xor_sync(0xffffffffu, hiA ? v0 : v2, 1);
        float t1 = __shfl_xor_sync(0xffffffffu, hiA ? v1 : v3, 1);
        float va = (hiA ? v2 : v0) + t0;
        float vb = (hiA ? v3 : v1) + t1;
        float t2 = __shfl_xor_sync(0xffffffffu, hiB ? va : vb, 2);
        acc = (hiB ? vb : va) + t2;
    }
    const int c_own = cg * 4 + (js & 1) * 2 + (js >> 1);

    const float inv = 1.0f / sDen[rr2];
    float val = g_h1[(size_t)(i0 + rr2) * HH + c_own] * fc_w[c_own]
              + acc * inv * fc_w[HH + c_own];
    #pragma unroll
    for (int off = 16; off; off >>= 1) val += __shfl_xor_sync(0xffffffffu, val, off);
    if (lane == 0) sRed[wid] = val;
    __syncthreads();
    if (tid < 8)
        out[i0 + tid] = sRed[tid * 2] + sRed[tid * 2 + 1] + fc_b[0];
}

// ---------------------------------------------------------------------------
// Launch: single stream; reldot is fused into the GRU kernel.
// ---------------------------------------------------------------------------
extern "C" void kernel_launch(void* const* d_in, const int* in_sizes, int n_in,
                              void* d_out, int out_size)
{
    const float* x    = (const float*)d_in[0];
    const float* rel  = (const float*)d_in[1];
    const float* W    = (const float*)d_in[2];
    const float* b    = (const float*)d_in[3];
    const float* fc_w = (const float*)d_in[4];
    const float* fc_b = (const float*)d_in[5];
    const float* Wih0 = (const float*)d_in[6];
    const float* Whh0 = (const float*)d_in[7];
    const float* bih0 = (const float*)d_in[8];
    const float* bhh0 = (const float*)d_in[9];
    const float* Wih1 = (const float*)d_in[10];
    const float* Whh1 = (const float*)d_in[11];
    const float* bih1 = (const float*)d_in[12];
    const float* bhh1 = (const float*)d_in[13];
    float* out = (float*)d_out;

    const size_t gru_smem =
        (3 * GG * W2 + GG * 8 + GRU_ROWS * 360 + 2 * 64 +
         4 * GRU_ROWS * H2 + RR) * sizeof(float);
    cudaFuncSetAttribute(gru_kernel, cudaFuncAttributeMaxDynamicSharedMemorySize,
                         (int)gru_smem);

    gru_kernel<<<NN / GRU_ROWS, GRU_THREADS, gru_smem>>>(
        x, rel, Wih0, Whh0, bih0, bhh0, Wih1, Whh1, bih1, bhh1, W);

    att4_kernel<<<NN / 8, A4_THREADS>>>(b, fc_w, fc_b, out);
}

// round 16
// speedup vs baseline: 1.2699x; 1.2699x over previous
#include <cuda_runtime.h>
#include <math.h>
#include <stdint.h>

// Problem constants
#define NN      1024
#define DF      6
#define TT      60
#define HH      64
#define GG      192      // 3*H
#define RR      64
#define W2      72       // weight row stride (words), kh-swizzled
#define H2      68       // h row stride (words), kh-swizzled
#define NEG_VAL (-10000.0f)
#define SLOPE   0.01f

// Inter-kernel scratch
__device__ float g_h1[NN * HH];
__device__ float g_sa[NN];
__device__ float g_sb[NN];
__device__ float g_dot[NN * NN];
__device__ float g_sum[NN * NN];

typedef unsigned long long u64;

__device__ __forceinline__ u64 ffma2(u64 a, u64 b, u64 c) {
    u64 d;
    asm("fma.rn.f32x2 %0, %1, %2, %3;" : "=l"(d) : "l"(a), "l"(b), "l"(c));
    return d;
}
__device__ __forceinline__ float hsum2(u64 v) {
    float lo, hi;
    asm("mov.b64 {%0,%1}, %2;" : "=f"(lo), "=f"(hi) : "l"(v));
    return lo + hi;
}
__device__ __forceinline__ float tanh_fast(float x) {
    float y;
    asm("tanh.approx.f32 %0, %1;" : "=f"(y) : "f"(x));
    return y;
}
__device__ __forceinline__ float sig_fast(float x) {
    return 0.5f * tanh_fast(0.5f * x) + 0.5f;
}

// Split-K pair reduction (partner = lane^1).
#define RED2(v0, v1, v2, v3, s0, s1)                                          \
    {                                                                         \
        float _ta = __shfl_xor_sync(0xffffffffu, kh ? (v0) : (v2), 1);        \
        float _tb = __shfl_xor_sync(0xffffffffu, kh ? (v1) : (v3), 1);        \
        (s0) = (kh ? (v2) : (v0)) + _ta;                                      \
        (s1) = (kh ? (v3) : (v1)) + _tb;                                      \
    }

// ---------------------------------------------------------------------------
// Kernel 1: fused 2-layer GRU v5 (R11/R14 proven: merged GEMM, 256 threads).
// ---------------------------------------------------------------------------
#define GRU_THREADS 256
#define GRU_ROWS    8

__global__ void __launch_bounds__(GRU_THREADS, 1)
gru_kernel(const float* __restrict__ x,
           const float* __restrict__ Wih0, const float* __restrict__ Whh0,
           const float* __restrict__ bih0, const float* __restrict__ bhh0,
           const float* __restrict__ Wih1, const float* __restrict__ Whh1,
           const float* __restrict__ bih1, const float* __restrict__ bhh1,
           const float* __restrict__ Wv)
{
    extern __shared__ float smem[];
    float* sWhh0 = smem;                          // 192*72
    float* sWih1 = sWhh0 + GG * W2;               // 192*72
    float* sWhh1 = sWih1 + GG * W2;               // 192*72
    float* sWih0 = sWhh1 + GG * W2;               // 192*8
    float* sX    = sWih0 + GG * 8;                // 8*360
    float* sXt   = sX + GRU_ROWS * 360;           // 2*64
    float* sH0   = sXt + 2 * 64;                  // 2*8*68
    float* sH1   = sH0 + 2 * GRU_ROWS * H2;       // 2*8*68

    const int tid = threadIdx.x;
    const int r0  = blockIdx.x * GRU_ROWS;

    for (int i = tid; i < GG * HH; i += GRU_THREADS) {
        int o = i >> 6, k = i & 63;
        int w = o * W2 + k + ((k >= 32) ? 4 : 0);
        sWhh0[w] = Whh0[i];
        sWih1[w] = Wih1[i];
        sWhh1[w] = Whh1[i];
    }
    for (int i = tid; i < GG * DF; i += GRU_THREADS) {
        int o = i / DF, d = i % DF;
        sWih0[o * 8 + d] = Wih0[i];
    }
    for (int i = tid; i < GRU_ROWS * 360; i += GRU_THREADS) {
        int r = i / 360, cc = i % 360;
        sX[i] = x[(size_t)(r0 + r) * 360 + cc];
    }
    for (int i = tid; i < 2 * GRU_ROWS * H2; i += GRU_THREADS) {
        sH0[i] = 0.f; sH1[i] = 0.f;
    }
    if (tid < GRU_ROWS * DF) {
        int r = tid / DF, d = tid % DF;
        sXt[r * 8 + d] = sX[r * 360 + d * TT + 0];
    }

    const int lane  = tid & 31;
    const int warp  = tid >> 5;
    const int kh    = lane & 1;
    const int rg    = (lane >> 1) & 1;
    const int cl    = lane >> 2;
    const int c     = warp * 8 + cl;
    const int rbase = rg * 4;
    const int R0    = rbase + 2 * kh;
    const int wob   = 36 * kh;
    const int swc   = (c >= 32) ? 4 : 0;

    const float br0  = bih0[c] + bhh0[c];
    const float bz0  = bih0[64 + c] + bhh0[64 + c];
    const float bxn0 = bih0[128 + c];
    const float bhn0 = bhh0[128 + c];
    const float br1  = bih1[c] + bhh1[c];
    const float bz1  = bih1[64 + c] + bhh1[64 + c];
    const float bxn1 = bih1[128 + c];
    const float bhn1 = bhh1[128 + c];
    __syncthreads();

    // ---- it = 0 ----
    {
        #pragma unroll
        for (int rr = 0; rr < 2; rr++) {
            int R = R0 + rr;
            float xr = 0.f, xz = 0.f, xn = 0.f;
            #pragma unroll
            for (int d = 0; d < DF; d++) {
                float xv = sXt[R * 8 + d];
                xr += xv * sWih0[c * 8 + d];
                xz += xv * sWih0[(64 + c) * 8 + d];
                xn += xv * sWih0[(128 + c) * 8 + d];
            }
            float rv = sig_fast(xr + br0);
            float zv = sig_fast(xz + bz0);
            float nv = tanh_fast(xn + bxn0 + rv * bhn0);
            sH0[1 * (GRU_ROWS * H2) + R * H2 + c + swc] = (1.f - zv) * nv;
        }
        if (tid < GRU_ROWS * DF) {
            int r = tid / DF, d = tid % DF;
            sXt[64 + r * 8 + d] = sX[r * 360 + d * TT + 1];
        }
    }
    __syncthreads();

    // ---- main loop ----
    for (int it = 1; it < TT; ++it) {
        const int pc = it & 1, pn = pc ^ 1;
        float* H0c = sH0 + pc * (GRU_ROWS * H2);
        float* H0n = sH0 + pn * (GRU_ROWS * H2);
        float* H1c = sH1 + pc * (GRU_ROWS * H2);
        float* H1n = sH1 + pn * (GRU_ROWS * H2);

        u64 Ar[4], Az[4], An[4], Br[4], Bz[4], Bxn[4], Bhn[4];
        #pragma unroll
        for (int i = 0; i < 4; i++) {
            Ar[i] = 0; Az[i] = 0; An[i] = 0;
            Br[i] = 0; Bz[i] = 0; Bxn[i] = 0; Bhn[i] = 0;
        }

        #pragma unroll
        for (int q = 0; q < 8; q++) {
            const int wo = wob + q * 4;
            ulonglong2 ar = *(const ulonglong2*)&sWhh0[c * W2 + wo];
            ulonglong2 az = *(const ulonglong2*)&sWhh0[(64 + c) * W2 + wo];
            ulonglong2 an = *(const ulonglong2*)&sWhh0[(128 + c) * W2 + wo];
            ulonglong2 ur = *(const ulonglong2*)&sWih1[c * W2 + wo];
            ulonglong2 uz = *(const ulonglong2*)&sWih1[(64 + c) * W2 + wo];
            ulonglong2 un = *(const ulonglong2*)&sWih1[(128 + c) * W2 + wo];
            ulonglong2 vr = *(const ulonglong2*)&sWhh1[c * W2 + wo];
            ulonglong2 vz = *(const ulonglong2*)&sWhh1[(64 + c) * W2 + wo];
            ulonglong2 vn = *(const ulonglong2*)&sWhh1[(128 + c) * W2 + wo];
            #pragma unroll
            for (int i = 0; i < 4; i++) {
                ulonglong2 h0v = *(const ulonglong2*)&H0c[(rbase + i) * H2 + wo];
                ulonglong2 h1v = *(const ulonglong2*)&H1c[(rbase + i) * H2 + wo];
                Ar[i]  = ffma2(h0v.x, ar.x, Ar[i]);
                Az[i]  = ffma2(h0v.x, az.x, Az[i]);
                An[i]  = ffma2(h0v.x, an.x, An[i]);
                Br[i]  = ffma2(h0v.x, ur.x, Br[i]);
                Bz[i]  = ffma2(h0v.x, uz.x, Bz[i]);
                Bxn[i] = ffma2(h0v.x, un.x, Bxn[i]);
                Br[i]  = ffma2(h1v.x, vr.x, Br[i]);
                Bz[i]  = ffma2(h1v.x, vz.x, Bz[i]);
                Bhn[i] = ffma2(h1v.x, vn.x, Bhn[i]);
                Ar[i]  = ffma2(h0v.y, ar.y, Ar[i]);
                Az[i]  = ffma2(h0v.y, az.y, Az[i]);
                An[i]  = ffma2(h0v.y, an.y, An[i]);
                Br[i]  = ffma2(h0v.y, ur.y, Br[i]);
                Bz[i]  = ffma2(h0v.y, uz.y, Bz[i]);
                Bxn[i] = ffma2(h0v.y, un.y, Bxn[i]);
                Br[i]  = ffma2(h1v.y, vr.y, Br[i]);
                Bz[i]  = ffma2(h1v.y, vz.y, Bz[i]);
                Bhn[i] = ffma2(h1v.y, vn.y, Bhn[i]);
            }
        }

        float sAr[2], sAz[2], sAn[2], sBr[2], sBz[2], sBxn[2], sBhn[2];
        {
            float v0, v1, v2, v3;
            v0 = hsum2(Ar[0]);  v1 = hsum2(Ar[1]);  v2 = hsum2(Ar[2]);  v3 = hsum2(Ar[3]);
            RED2(v0, v1, v2, v3, sAr[0], sAr[1]);
            v0 = hsum2(Az[0]);  v1 = hsum2(Az[1]);  v2 = hsum2(Az[2]);  v3 = hsum2(Az[3]);
            RED2(v0, v1, v2, v3, sAz[0], sAz[1]);
            v0 = hsum2(An[0]);  v1 = hsum2(An[1]);  v2 = hsum2(An[2]);  v3 = hsum2(An[3]);
            RED2(v0, v1, v2, v3, sAn[0], sAn[1]);
            v0 = hsum2(Br[0]);  v1 = hsum2(Br[1]);  v2 = hsum2(Br[2]);  v3 = hsum2(Br[3]);
            RED2(v0, v1, v2, v3, sBr[0], sBr[1]);
            v0 = hsum2(Bz[0]);  v1 = hsum2(Bz[1]);  v2 = hsum2(Bz[2]);  v3 = hsum2(Bz[3]);
            RED2(v0, v1, v2, v3, sBz[0], sBz[1]);
            v0 = hsum2(Bxn[0]); v1 = hsum2(Bxn[1]); v2 = hsum2(Bxn[2]); v3 = hsum2(Bxn[3]);
            RED2(v0, v1, v2, v3, sBxn[0], sBxn[1]);
            v0 = hsum2(Bhn[0]); v1 = hsum2(Bhn[1]); v2 = hsum2(Bhn[2]); v3 = hsum2(Bhn[3]);
            RED2(v0, v1, v2, v3, sBhn[0], sBhn[1]);
        }

        #pragma unroll
        for (int rr = 0; rr < 2; rr++) {
            int R = R0 + rr;
            float xr = 0.f, xz = 0.f, xn = 0.f;
            #pragma unroll
            for (int d = 0; d < DF; d++) {
                float xv = sXt[pc * 64 + R * 8 + d];
                xr += xv * sWih0[c * 8 + d];
                xz += xv * sWih0[(64 + c) * 8 + d];
                xn += xv * sWih0[(128 + c) * 8 + d];
            }
            float rv = sig_fast(xr + sAr[rr] + br0);
            float zv = sig_fast(xz + sAz[rr] + bz0);
            float nv = tanh_fast(xn + bxn0 + rv * (sAn[rr] + bhn0));
            float h0old = H0c[R * H2 + c + swc];
            H0n[R * H2 + c + swc] = (1.f - zv) * nv + zv * h0old;

            float rv1 = sig_fast(sBr[rr] + br1);
            float zv1 = sig_fast(sBz[rr] + bz1);
            float nv1 = tanh_fast(sBxn[rr] + bxn1 + rv1 * (sBhn[rr] + bhn1));
            float h1old = H1c[R * H2 + c + swc];
            H1n[R * H2 + c + swc] = (1.f - zv1) * nv1 + zv1 * h1old;
        }
        if (it + 1 < TT && tid < GRU_ROWS * DF) {
            int r = tid / DF, d = tid % DF;
            sXt[pn * 64 + r * 8 + d] = sX[r * 360 + d * TT + (it + 1)];
        }
        __syncthreads();
    }

    // ---- epilogue: final L1 step -> h1[TT] ----
    {
        float* H0c = sH0 + ((TT) & 1) * (GRU_ROWS * H2);
        float* H1c = sH1 + ((TT) & 1) * (GRU_ROWS * H2);
        float* H1f = sH1 + (((TT) & 1) ^ 1) * (GRU_ROWS * H2);

        u64 Br[4], Bz[4], Bxn[4], Bhn[4];
        #pragma unroll
        for (int i = 0; i < 4; i++) { Br[i] = 0; Bz[i] = 0; Bxn[i] = 0; Bhn[i] = 0; }

        #pragma unroll
        for (int q = 0; q < 8; q++) {
            const int wo = wob + q * 4;
            ulonglong2 ur = *(const ulonglong2*)&sWih1[c * W2 + wo];
            ulonglong2 uz = *(const ulonglong2*)&sWih1[(64 + c) * W2 + wo];
            ulonglong2 un = *(const ulonglong2*)&sWih1[(128 + c) * W2 + wo];
            ulonglong2 vr = *(const ulonglong2*)&sWhh1[c * W2 + wo];
            ulonglong2 vz = *(const ulonglong2*)&sWhh1[(64 + c) * W2 + wo];
            ulonglong2 vn = *(const ulonglong2*)&sWhh1[(128 + c) * W2 + wo];
            #pragma unroll
            for (int i = 0; i < 4; i++) {
                ulonglong2 h0v = *(const ulonglong2*)&H0c[(rbase + i) * H2 + wo];
                ulonglong2 h1v = *(const ulonglong2*)&H1c[(rbase + i) * H2 + wo];
                Br[i]  = ffma2(h0v.x, ur.x, Br[i]);
                Bz[i]  = ffma2(h0v.x, uz.x, Bz[i]);
                Bxn[i] = ffma2(h0v.x, un.x, Bxn[i]);
                Br[i]  = ffma2(h1v.x, vr.x, Br[i]);
                Bz[i]  = ffma2(h1v.x, vz.x, Bz[i]);
                Bhn[i] = ffma2(h1v.x, vn.x, Bhn[i]);
                Br[i]  = ffma2(h0v.y, ur.y, Br[i]);
                Bz[i]  = ffma2(h0v.y, uz.y, Bz[i]);
                Bxn[i] = ffma2(h0v.y, un.y, Bxn[i]);
                Br[i]  = ffma2(h1v.y, vr.y, Br[i]);
                Bz[i]  = ffma2(h1v.y, vz.y, Bz[i]);
                Bhn[i] = ffma2(h1v.y, vn.y, Bhn[i]);
            }
        }
        float sBr[2], sBz[2], sBxn[2], sBhn[2];
        {
            float v0, v1, v2, v3;
            v0 = hsum2(Br[0]);  v1 = hsum2(Br[1]);  v2 = hsum2(Br[2]);  v3 = hsum2(Br[3]);
            RED2(v0, v1, v2, v3, sBr[0], sBr[1]);
            v0 = hsum2(Bz[0]);  v1 = hsum2(Bz[1]);  v2 = hsum2(Bz[2]);  v3 = hsum2(Bz[3]);
            RED2(v0, v1, v2, v3, sBz[0], sBz[1]);
            v0 = hsum2(Bxn[0]); v1 = hsum2(Bxn[1]); v2 = hsum2(Bxn[2]); v3 = hsum2(Bxn[3]);
            RED2(v0, v1, v2, v3, sBxn[0], sBxn[1]);
            v0 = hsum2(Bhn[0]); v1 = hsum2(Bhn[1]); v2 = hsum2(Bhn[2]); v3 = hsum2(Bhn[3]);
            RED2(v0, v1, v2, v3, sBhn[0], sBhn[1]);
        }
        #pragma unroll
        for (int rr = 0; rr < 2; rr++) {
            int R = R0 + rr;
            float rv1 = sig_fast(sBr[rr] + br1);
            float zv1 = sig_fast(sBz[rr] + bz1);
            float nv1 = tanh_fast(sBxn[rr] + bxn1 + rv1 * (sBhn[rr] + bhn1));
            float h1old = H1c[R * H2 + c + swc];
            H1f[R * H2 + c + swc] = (1.f - zv1) * nv1 + zv1 * h1old;
        }
    }
    __syncthreads();

    // ---- outputs (unswizzle) ----
    const float* hf = sH1 + (((TT) & 1) ^ 1) * (GRU_ROWS * H2);
    for (int i = tid; i < GRU_ROWS * HH; i += GRU_THREADS) {
        int r = i >> 6, cc = i & 63;
        g_h1[(size_t)r0 * HH + i] = hf[r * H2 + cc + ((cc >= 32) ? 4 : 0)];
    }
    if (tid < GRU_ROWS) {
        float a = 0.f, b2s = 0.f;
        #pragma unroll
        for (int cc = 0; cc < HH; cc++) {
            float h = hf[tid * H2 + cc + ((cc >= 32) ? 4 : 0)];
            a   += h * Wv[cc];
            b2s += h * Wv[HH + cc];
        }
        g_sa[r0 + tid] = a;
        g_sb[r0 + tid] = b2s;
    }
}

// ---------------------------------------------------------------------------
// Kernel 2: streaming rel-dot (R6 proven version).
// ---------------------------------------------------------------------------
#define RD_THREADS 256
#define RD_BLOCKS  2048

__global__ void __launch_bounds__(RD_THREADS)
reldot_kernel(const float* __restrict__ rel, const float* __restrict__ W)
{
    __shared__ float sWv[RR];
    const int tid = threadIdx.x;
    if (tid < RR) sWv[tid] = W[2 * HH + tid];
    __syncthreads();

    const int lane16 = tid & 15;
    const int grp    = tid >> 4;
    const float4 wv  = *(const float4*)&sWv[lane16 * 4];
    const int stride = RD_BLOCKS * 16;

    for (int p = blockIdx.x * 16 + grp; p < NN * NN; p += stride) {
        float4 v = *(const float4*)&rel[(size_t)p * RR + lane16 * 4];
        float dot  = v.x * wv.x + v.y * wv.y + v.z * wv.z + v.w * wv.w;
        float ssum = v.x + v.y + v.z + v.w;
        #pragma unroll
        for (int off = 8; off; off >>= 1) {
            dot  += __shfl_xor_sync(0xffffffffu, dot,  off);
            ssum += __shfl_xor_sync(0xffffffffu, ssum, off);
        }
        if (lane16 == 0) {
            g_dot[p] = dot;
            g_sum[p] = ssum;
        }
    }
}

// ---------------------------------------------------------------------------
// Kernel 3: softmax + agg + FC v5 — double-buffered tile pipeline,
// one barrier per tile, prefetch overlapped with compute.
// ---------------------------------------------------------------------------
#define A5_THREADS 512
#define TLD 72

__global__ void __launch_bounds__(A5_THREADS)
att5_kernel(const float* __restrict__ bsc,
            const float* __restrict__ fc_w,
            const float* __restrict__ fc_b,
            float* __restrict__ out)
{
    __shared__ float sP[8 * NN];          // 32 KB
    __shared__ float sT[2][64 * TLD];     // 2 x 18 KB (double buffer)
    __shared__ float sWmax[16];
    __shared__ float sWsum[16];
    __shared__ float sDen[8];
    __shared__ float sRed[16];

    const int tid  = threadIdx.x;
    const int wid  = tid >> 5;
    const int lane = tid & 31;
    const int i0   = blockIdx.x * 8;

    // ---- softmax phase (2 warps per row) ----
    const int r    = wid >> 1;
    const int part = ((wid & 1) << 5) + lane;
    const int i    = i0 + r;
    const float sa_i = g_sa[i];
    const float bval = bsc[0];

    float tv[16];
    float mx = -INFINITY;
    #pragma unroll
    for (int q4 = 0; q4 < 4; q4++) {
        int j = part * 16 + q4 * 4;
        float4 d4 = *(const float4*)&g_dot[(size_t)i * NN + j];
        float4 s4 = *(const float4*)&g_sum[(size_t)i * NN + j];
        #pragma unroll
        for (int e = 0; e < 4; e++) {
            float dot  = (&d4.x)[e];
            float ssum = (&s4.x)[e];
            float w = sa_i + g_sb[j + e] + dot + bval;
            w = (w >= 0.f) ? w : SLOPE * w;
            float m  = (ssum != 0.f) ? 1.f : 0.f;
            float t  = m * w;
            if (t == 0.f) t = NEG_VAL;
            tv[q4 * 4 + e] = t;
            sP[r * NN + j + e] = m;
            mx = fmaxf(mx, t);
        }
    }
    #pragma unroll
    for (int off = 16; off; off >>= 1) mx = fmaxf(mx, __shfl_xor_sync(0xffffffffu, mx, off));
    if (lane == 0) sWmax[wid] = mx;
    __syncthreads();
    mx = fmaxf(sWmax[r * 2], sWmax[r * 2 + 1]);

    float lsum = 0.f;
    #pragma unroll
    for (int q = 0; q < 16; q++) {
        int j = part * 16 + q;
        float e = __expf(tv[q] - mx);
        lsum += e;
        sP[r * NN + j] = e * sP[r * NN + j];
    }
    #pragma unroll
    for (int off = 16; off; off >>= 1) lsum += __shfl_xor_sync(0xffffffffu, lsum, off);
    if (lane == 0) sWsum[wid] = lsum;
    __syncthreads();
    if (tid < 8) sDen[tid] = sWsum[tid * 2] + sWsum[tid * 2 + 1];

    // ---- agg phase: pipelined tiles ----
    const int js  = tid & 3;
    const int cg  = (tid >> 2) & 15;
    const int rr2 = tid >> 6;
    const int fr0 = tid >> 4, fc0 = (tid & 15) * 4;              // STS target row/col (k=0)
    const int fr1 = (tid + A5_THREADS) >> 4;                     // (k=1)

    // prologue: load + store tile 0, then barrier (also covers sP/sDen)
    float4 pf0 = *(const float4*)&g_h1[(size_t)tid * 4];
    float4 pf1 = *(const float4*)&g_h1[(size_t)(tid + A5_THREADS) * 4];
    *(float4*)&sT[0][fr0 * TLD + fc0] = pf0;
    *(float4*)&sT[0][fr1 * TLD + fc0] = pf1;
    __syncthreads();

    u64 a0 = 0, a1 = 0;
    for (int tile = 0; tile < 16; tile++) {
        const int cur = tile & 1, nxt = cur ^ 1;

        // prefetch next tile (overlaps with compute below)
        if (tile < 15) {
            pf0 = *(const float4*)&g_h1[(size_t)(tile + 1) * 4096 + (size_t)tid * 4];
            pf1 = *(const float4*)&g_h1[(size_t)(tile + 1) * 4096 + (size_t)(tid + A5_THREADS) * 4];
        }

        const float* pr = &sP[rr2 * NN + tile * 64];
        const float* tb = sT[cur];
        #pragma unroll
        for (int jj = 0; jj < 16; jj++) {
            int jl = jj * 4 + js;
            float p = pr[jl];
            u64 pp;
            asm("mov.b64 %0, {%1, %1};" : "=l"(pp) : "f"(p));
            ulonglong2 tvv = *(const ulonglong2*)&tb[jl * TLD + cg * 4];
            a0 = ffma2(pp, tvv.x, a0);
            a1 = ffma2(pp, tvv.y, a1);
        }

        if (tile < 15) {
            *(float4*)&sT[nxt][fr0 * TLD + fc0] = pf0;
            *(float4*)&sT[nxt][fr1 * TLD + fc0] = pf1;
            __syncthreads();
        }
    }

    // compacting 4-way js reduction; owner col = cg*4 + (js&1)*2 + (js>>1)
    float acc;
    {
        float v0, v1, v2, v3;
        asm("mov.b64 {%0,%1}, %2;" : "=f"(v0), "=f"(v1) : "l"(a0));
        asm("mov.b64 {%0,%1}, %2;" : "=f"(v2), "=f"(v3) : "l"(a1));
        const bool hiA = (js & 1);
        const bool hiB = ((js >> 1) & 1);
        float t0 = __shfl_xor_sync(0xffffffffu, hiA ? v0 : v2, 1);
        float t1 = __shfl_xor_sync(0xffffffffu, hiA ? v1 : v3, 1);
        float va = (hiA ? v2 : v0) + t0;
        float vb = (hiA ? v3 : v1) + t1;
        float t2 = __shfl_xor_sync(0xffffffffu, hiB ? va : vb, 2);
        acc = (hiB ? vb : va) + t2;
    }
    const int c_own = cg * 4 + (js & 1) * 2 + (js >> 1);

    const float inv = 1.0f / sDen[rr2];
    float val = g_h1[(size_t)(i0 + rr2) * HH + c_own] * fc_w[c_own]
              + acc * inv * fc_w[HH + c_own];
    #pragma unroll
    for (int off = 16; off; off >>= 1) val += __shfl_xor_sync(0xffffffffu, val, off);
    if (lane == 0) sRed[wid] = val;
    __syncthreads();
    if (tid < 8)
        out[i0 + tid] = sRed[tid * 2] + sRed[tid * 2 + 1] + fc_b[0];
}

// ---------------------------------------------------------------------------
// Launch: gru first on main stream, reldot forked alongside it.
// ---------------------------------------------------------------------------
extern "C" void kernel_launch(void* const* d_in, const int* in_sizes, int n_in,
                              void* d_out, int out_size)
{
    const float* x    = (const float*)d_in[0];
    const float* rel  = (const float*)d_in[1];
    const float* W    = (const float*)d_in[2];
    const float* b    = (const float*)d_in[3];
    const float* fc_w = (const float*)d_in[4];
    const float* fc_b = (const float*)d_in[5];
    const float* Wih0 = (const float*)d_in[6];
    const float* Whh0 = (const float*)d_in[7];
    const float* bih0 = (const float*)d_in[8];
    const float* bhh0 = (const float*)d_in[9];
    const float* Wih1 = (const float*)d_in[10];
    const float* Whh1 = (const float*)d_in[11];
    const float* bih1 = (const float*)d_in[12];
    const float* bhh1 = (const float*)d_in[13];
    float* out = (float*)d_out;

    const size_t gru_smem =
        (3 * GG * W2 + GG * 8 + GRU_ROWS * 360 + 2 * 64 +
         4 * GRU_ROWS * H2) * sizeof(float);
    cudaFuncSetAttribute(gru_kernel, cudaFuncAttributeMaxDynamicSharedMemorySize,
                         (int)gru_smem);

    cudaStream_t s1;
    cudaEvent_t eFork, eJoin;
    cudaStreamCreateWithFlags(&s1, cudaStreamNonBlocking);
    cudaEventCreateWithFlags(&eFork, cudaEventDisableTiming);
    cudaEventCreateWithFlags(&eJoin, cudaEventDisableTiming);

    cudaEventRecord(eFork, 0);
    cudaStreamWaitEvent(s1, eFork, 0);

    gru_kernel<<<NN / GRU_ROWS, GRU_THREADS, gru_smem>>>(
        x, Wih0, Whh0, bih0, bhh0, Wih1, Whh1, bih1, bhh1, W);

    reldot_kernel<<<RD_BLOCKS, RD_THREADS, 0, s1>>>(rel, W);
    cudaEventRecord(eJoin, s1);

    cudaStreamWaitEvent(0, eJoin, 0);

    att5_kernel<<<NN / 8, A5_THREADS>>>(b, fc_w, fc_b, out);
}

// round 17
// speedup vs baseline: 1.2780x; 1.0063x over previous
#include <cuda_runtime.h>
#include <math.h>
#include <stdint.h>

// Problem constants
#define NN      1024
#define DF      6
#define TT      60
#define HH      64
#define GG      192      // 3*H
#define RR      64
#define W2      72       // weight row stride (words), kh-swizzled
#define H2      68       // h row stride (words), kh-swizzled
#define NEG_VAL (-10000.0f)
#define SLOPE   0.01f

// Inter-kernel scratch
__device__ float g_h1[NN * HH];
__device__ float g_sa[NN];
__device__ float g_sb[NN];
__device__ float g_dot[NN * NN];
__device__ float g_sum[NN * NN];

typedef unsigned long long u64;

__device__ __forceinline__ u64 ffma2(u64 a, u64 b, u64 c) {
    u64 d;
    asm("fma.rn.f32x2 %0, %1, %2, %3;" : "=l"(d) : "l"(a), "l"(b), "l"(c));
    return d;
}
__device__ __forceinline__ u64 add2(u64 a, u64 b) {
    u64 d;
    asm("add.rn.f32x2 %0, %1, %2;" : "=l"(d) : "l"(a), "l"(b));
    return d;
}
__device__ __forceinline__ float hsum2(u64 v) {
    float lo, hi;
    asm("mov.b64 {%0,%1}, %2;" : "=f"(lo), "=f"(hi) : "l"(v));
    return lo + hi;
}
__device__ __forceinline__ float tanh_fast(float x) {
    float y;
    asm("tanh.approx.f32 %0, %1;" : "=f"(y) : "f"(x));
    return y;
}
__device__ __forceinline__ float sig_fast(float x) {
    return 0.5f * tanh_fast(0.5f * x) + 0.5f;
}

// Split-K pair reduction (partner = lane^1).
#define RED2(v0, v1, v2, v3, s0, s1)                                          \
    {                                                                         \
        float _ta = __shfl_xor_sync(0xffffffffu, kh ? (v0) : (v2), 1);        \
        float _tb = __shfl_xor_sync(0xffffffffu, kh ? (v1) : (v3), 1);        \
        (s0) = (kh ? (v2) : (v0)) + _ta;                                      \
        (s1) = (kh ? (v3) : (v1)) + _tb;                                      \
    }

// ---------------------------------------------------------------------------
// Kernel 1: fused 2-layer GRU v5 (R11 proven: merged GEMM, 256 threads).
// ---------------------------------------------------------------------------
#define GRU_THREADS 256
#define GRU_ROWS    8

__global__ void __launch_bounds__(GRU_THREADS, 1)
gru_kernel(const float* __restrict__ x,
           const float* __restrict__ Wih0, const float* __restrict__ Whh0,
           const float* __restrict__ bih0, const float* __restrict__ bhh0,
           const float* __restrict__ Wih1, const float* __restrict__ Whh1,
           const float* __restrict__ bih1, const float* __restrict__ bhh1,
           const float* __restrict__ Wv)
{
    extern __shared__ float smem[];
    float* sWhh0 = smem;                          // 192*72
    float* sWih1 = sWhh0 + GG * W2;               // 192*72
    float* sWhh1 = sWih1 + GG * W2;               // 192*72
    float* sWih0 = sWhh1 + GG * W2;               // 192*8
    float* sX    = sWih0 + GG * 8;                // 8*360
    float* sXt   = sX + GRU_ROWS * 360;           // 2*64
    float* sH0   = sXt + 2 * 64;                  // 2*8*68
    float* sH1   = sH0 + 2 * GRU_ROWS * H2;       // 2*8*68

    const int tid = threadIdx.x;
    const int r0  = blockIdx.x * GRU_ROWS;

    for (int i = tid; i < GG * HH; i += GRU_THREADS) {
        int o = i >> 6, k = i & 63;
        int w = o * W2 + k + ((k >= 32) ? 4 : 0);
        sWhh0[w] = Whh0[i];
        sWih1[w] = Wih1[i];
        sWhh1[w] = Whh1[i];
    }
    for (int i = tid; i < GG * DF; i += GRU_THREADS) {
        int o = i / DF, d = i % DF;
        sWih0[o * 8 + d] = Wih0[i];
    }
    for (int i = tid; i < GRU_ROWS * 360; i += GRU_THREADS) {
        int r = i / 360, cc = i % 360;
        sX[i] = x[(size_t)(r0 + r) * 360 + cc];
    }
    for (int i = tid; i < 2 * GRU_ROWS * H2; i += GRU_THREADS) {
        sH0[i] = 0.f; sH1[i] = 0.f;
    }
    if (tid < GRU_ROWS * DF) {
        int r = tid / DF, d = tid % DF;
        sXt[r * 8 + d] = sX[r * 360 + d * TT + 0];
    }

    const int lane  = tid & 31;
    const int warp  = tid >> 5;
    const int kh    = lane & 1;
    const int rg    = (lane >> 1) & 1;
    const int cl    = lane >> 2;
    const int c     = warp * 8 + cl;
    const int rbase = rg * 4;
    const int R0    = rbase + 2 * kh;
    const int wob   = 36 * kh;
    const int swc   = (c >= 32) ? 4 : 0;

    const float br0  = bih0[c] + bhh0[c];
    const float bz0  = bih0[64 + c] + bhh0[64 + c];
    const float bxn0 = bih0[128 + c];
    const float bhn0 = bhh0[128 + c];
    const float br1  = bih1[c] + bhh1[c];
    const float bz1  = bih1[64 + c] + bhh1[64 + c];
    const float bxn1 = bih1[128 + c];
    const float bhn1 = bhh1[128 + c];
    __syncthreads();

    // ---- it = 0 ----
    {
        #pragma unroll
        for (int rr = 0; rr < 2; rr++) {
            int R = R0 + rr;
            float xr = 0.f, xz = 0.f, xn = 0.f;
            #pragma unroll
            for (int d = 0; d < DF; d++) {
                float xv = sXt[R * 8 + d];
                xr += xv * sWih0[c * 8 + d];
                xz += xv * sWih0[(64 + c) * 8 + d];
                xn += xv * sWih0[(128 + c) * 8 + d];
            }
            float rv = sig_fast(xr + br0);
            float zv = sig_fast(xz + bz0);
            float nv = tanh_fast(xn + bxn0 + rv * bhn0);
            sH0[1 * (GRU_ROWS * H2) + R * H2 + c + swc] = (1.f - zv) * nv;
        }
        if (tid < GRU_ROWS * DF) {
            int r = tid / DF, d = tid % DF;
            sXt[64 + r * 8 + d] = sX[r * 360 + d * TT + 1];
        }
    }
    __syncthreads();

    // ---- main loop ----
    for (int it = 1; it < TT; ++it) {
        const int pc = it & 1, pn = pc ^ 1;
        float* H0c = sH0 + pc * (GRU_ROWS * H2);
        float* H0n = sH0 + pn * (GRU_ROWS * H2);
        float* H1c = sH1 + pc * (GRU_ROWS * H2);
        float* H1n = sH1 + pn * (GRU_ROWS * H2);

        u64 Ar[4], Az[4], An[4], Br[4], Bz[4], Bxn[4], Bhn[4];
        #pragma unroll
        for (int i = 0; i < 4; i++) {
            Ar[i] = 0; Az[i] = 0; An[i] = 0;
            Br[i] = 0; Bz[i] = 0; Bxn[i] = 0; Bhn[i] = 0;
        }

        #pragma unroll
        for (int q = 0; q < 8; q++) {
            const int wo = wob + q * 4;
            ulonglong2 ar = *(const ulonglong2*)&sWhh0[c * W2 + wo];
            ulonglong2 az = *(const ulonglong2*)&sWhh0[(64 + c) * W2 + wo];
            ulonglong2 an = *(const ulonglong2*)&sWhh0[(128 + c) * W2 + wo];
            ulonglong2 ur = *(const ulonglong2*)&sWih1[c * W2 + wo];
            ulonglong2 uz = *(const ulonglong2*)&sWih1[(64 + c) * W2 + wo];
            ulonglong2 un = *(const ulonglong2*)&sWih1[(128 + c) * W2 + wo];
            ulonglong2 vr = *(const ulonglong2*)&sWhh1[c * W2 + wo];
            ulonglong2 vz = *(const ulonglong2*)&sWhh1[(64 + c) * W2 + wo];
            ulonglong2 vn = *(const ulonglong2*)&sWhh1[(128 + c) * W2 + wo];
            #pragma unroll
            for (int i = 0; i < 4; i++) {
                ulonglong2 h0v = *(const ulonglong2*)&H0c[(rbase + i) * H2 + wo];
                ulonglong2 h1v = *(const ulonglong2*)&H1c[(rbase + i) * H2 + wo];
                Ar[i]  = ffma2(h0v.x, ar.x, Ar[i]);
                Az[i]  = ffma2(h0v.x, az.x, Az[i]);
                An[i]  = ffma2(h0v.x, an.x, An[i]);
                Br[i]  = ffma2(h0v.x, ur.x, Br[i]);
                Bz[i]  = ffma2(h0v.x, uz.x, Bz[i]);
                Bxn[i] = ffma2(h0v.x, un.x, Bxn[i]);
                Br[i]  = ffma2(h1v.x, vr.x, Br[i]);
                Bz[i]  = ffma2(h1v.x, vz.x, Bz[i]);
                Bhn[i] = ffma2(h1v.x, vn.x, Bhn[i]);
                Ar[i]  = ffma2(h0v.y, ar.y, Ar[i]);
                Az[i]  = ffma2(h0v.y, az.y, Az[i]);
                An[i]  = ffma2(h0v.y, an.y, An[i]);
                Br[i]  = ffma2(h0v.y, ur.y, Br[i]);
                Bz[i]  = ffma2(h0v.y, uz.y, Bz[i]);
                Bxn[i] = ffma2(h0v.y, un.y, Bxn[i]);
                Br[i]  = ffma2(h1v.y, vr.y, Br[i]);
                Bz[i]  = ffma2(h1v.y, vz.y, Bz[i]);
                Bhn[i] = ffma2(h1v.y, vn.y, Bhn[i]);
            }
        }

        float sAr[2], sAz[2], sAn[2], sBr[2], sBz[2], sBxn[2], sBhn[2];
        {
            float v0, v1, v2, v3;
            v0 = hsum2(Ar[0]);  v1 = hsum2(Ar[1]);  v2 = hsum2(Ar[2]);  v3 = hsum2(Ar[3]);
            RED2(v0, v1, v2, v3, sAr[0], sAr[1]);
            v0 = hsum2(Az[0]);  v1 = hsum2(Az[1]);  v2 = hsum2(Az[2]);  v3 = hsum2(Az[3]);
            RED2(v0, v1, v2, v3, sAz[0], sAz[1]);
            v0 = hsum2(An[0]);  v1 = hsum2(An[1]);  v2 = hsum2(An[2]);  v3 = hsum2(An[3]);
            RED2(v0, v1, v2, v3, sAn[0], sAn[1]);
            v0 = hsum2(Br[0]);  v1 = hsum2(Br[1]);  v2 = hsum2(Br[2]);  v3 = hsum2(Br[3]);
            RED2(v0, v1, v2, v3, sBr[0], sBr[1]);
            v0 = hsum2(Bz[0]);  v1 = hsum2(Bz[1]);  v2 = hsum2(Bz[2]);  v3 = hsum2(Bz[3]);
            RED2(v0, v1, v2, v3, sBz[0], sBz[1]);
            v0 = hsum2(Bxn[0]); v1 = hsum2(Bxn[1]); v2 = hsum2(Bxn[2]); v3 = hsum2(Bxn[3]);
            RED2(v0, v1, v2, v3, sBxn[0], sBxn[1]);
            v0 = hsum2(Bhn[0]); v1 = hsum2(Bhn[1]); v2 = hsum2(Bhn[2]); v3 = hsum2(Bhn[3]);
            RED2(v0, v1, v2, v3, sBhn[0], sBhn[1]);
        }

        #pragma unroll
        for (int rr = 0; rr < 2; rr++) {
            int R = R0 + rr;
            float xr = 0.f, xz = 0.f, xn = 0.f;
            #pragma unroll
            for (int d = 0; d < DF; d++) {
                float xv = sXt[pc * 64 + R * 8 + d];
                xr += xv * sWih0[c * 8 + d];
                xz += xv * sWih0[(64 + c) * 8 + d];
                xn += xv * sWih0[(128 + c) * 8 + d];
            }
            float rv = sig_fast(xr + sAr[rr] + br0);
            float zv = sig_fast(xz + sAz[rr] + bz0);
            float nv = tanh_fast(xn + bxn0 + rv * (sAn[rr] + bhn0));
            float h0old = H0c[R * H2 + c + swc];
            H0n[R * H2 + c + swc] = (1.f - zv) * nv + zv * h0old;

            float rv1 = sig_fast(sBr[rr] + br1);
            float zv1 = sig_fast(sBz[rr] + bz1);
            float nv1 = tanh_fast(sBxn[rr] + bxn1 + rv1 * (sBhn[rr] + bhn1));
            float h1old = H1c[R * H2 + c + swc];
            H1n[R * H2 + c + swc] = (1.f - zv1) * nv1 + zv1 * h1old;
        }
        if (it + 1 < TT && tid < GRU_ROWS * DF) {
            int r = tid / DF, d = tid % DF;
            sXt[pn * 64 + r * 8 + d] = sX[r * 360 + d * TT + (it + 1)];
        }
        __syncthreads();
    }

    // ---- epilogue: final L1 step -> h1[TT] ----
    {
        float* H0c = sH0 + ((TT) & 1) * (GRU_ROWS * H2);
        float* H1c = sH1 + ((TT) & 1) * (GRU_ROWS * H2);
        float* H1f = sH1 + (((TT) & 1) ^ 1) * (GRU_ROWS * H2);

        u64 Br[4], Bz[4], Bxn[4], Bhn[4];
        #pragma unroll
        for (int i = 0; i < 4; i++) { Br[i] = 0; Bz[i] = 0; Bxn[i] = 0; Bhn[i] = 0; }

        #pragma unroll
        for (int q = 0; q < 8; q++) {
            const int wo = wob + q * 4;
            ulonglong2 ur = *(const ulonglong2*)&sWih1[c * W2 + wo];
            ulonglong2 uz = *(const ulonglong2*)&sWih1[(64 + c) * W2 + wo];
            ulonglong2 un = *(const ulonglong2*)&sWih1[(128 + c) * W2 + wo];
            ulonglong2 vr = *(const ulonglong2*)&sWhh1[c * W2 + wo];
            ulonglong2 vz = *(const ulonglong2*)&sWhh1[(64 + c) * W2 + wo];
            ulonglong2 vn = *(const ulonglong2*)&sWhh1[(128 + c) * W2 + wo];
            #pragma unroll
            for (int i = 0; i < 4; i++) {
                ulonglong2 h0v = *(const ulonglong2*)&H0c[(rbase + i) * H2 + wo];
                ulonglong2 h1v = *(const ulonglong2*)&H1c[(rbase + i) * H2 + wo];
                Br[i]  = ffma2(h0v.x, ur.x, Br[i]);
                Bz[i]  = ffma2(h0v.x, uz.x, Bz[i]);
                Bxn[i] = ffma2(h0v.x, un.x, Bxn[i]);
                Br[i]  = ffma2(h1v.x, vr.x, Br[i]);
                Bz[i]  = ffma2(h1v.x, vz.x, Bz[i]);
                Bhn[i] = ffma2(h1v.x, vn.x, Bhn[i]);
                Br[i]  = ffma2(h0v.y, ur.y, Br[i]);
                Bz[i]  = ffma2(h0v.y, uz.y, Bz[i]);
                Bxn[i] = ffma2(h0v.y, un.y, Bxn[i]);
                Br[i]  = ffma2(h1v.y, vr.y, Br[i]);
                Bz[i]  = ffma2(h1v.y, vz.y, Bz[i]);
                Bhn[i] = ffma2(h1v.y, vn.y, Bhn[i]);
            }
        }
        float sBr[2], sBz[2], sBxn[2], sBhn[2];
        {
            float v0, v1, v2, v3;
            v0 = hsum2(Br[0]);  v1 = hsum2(Br[1]);  v2 = hsum2(Br[2]);  v3 = hsum2(Br[3]);
            RED2(v0, v1, v2, v3, sBr[0], sBr[1]);
            v0 = hsum2(Bz[0]);  v1 = hsum2(Bz[1]);  v2 = hsum2(Bz[2]);  v3 = hsum2(Bz[3]);
            RED2(v0, v1, v2, v3, sBz[0], sBz[1]);
            v0 = hsum2(Bxn[0]); v1 = hsum2(Bxn[1]); v2 = hsum2(Bxn[2]); v3 = hsum2(Bxn[3]);
            RED2(v0, v1, v2, v3, sBxn[0], sBxn[1]);
            v0 = hsum2(Bhn[0]); v1 = hsum2(Bhn[1]); v2 = hsum2(Bhn[2]); v3 = hsum2(Bhn[3]);
            RED2(v0, v1, v2, v3, sBhn[0], sBhn[1]);
        }
        #pragma unroll
        for (int rr = 0; rr < 2; rr++) {
            int R = R0 + rr;
            float rv1 = sig_fast(sBr[rr] + br1);
            float zv1 = sig_fast(sBz[rr] + bz1);
            float nv1 = tanh_fast(sBxn[rr] + bxn1 + rv1 * (sBhn[rr] + bhn1));
            float h1old = H1c[R * H2 + c + swc];
            H1f[R * H2 + c + swc] = (1.f - zv1) * nv1 + zv1 * h1old;
        }
    }
    __syncthreads();

    // ---- outputs (unswizzle) ----
    const float* hf = sH1 + (((TT) & 1) ^ 1) * (GRU_ROWS * H2);
    for (int i = tid; i < GRU_ROWS * HH; i += GRU_THREADS) {
        int r = i >> 6, cc = i & 63;
        g_h1[(size_t)r0 * HH + i] = hf[r * H2 + cc + ((cc >= 32) ? 4 : 0)];
    }
    if (tid < GRU_ROWS) {
        float a = 0.f, b2s = 0.f;
        #pragma unroll
        for (int cc = 0; cc < HH; cc++) {
            float h = hf[tid * H2 + cc + ((cc >= 32) ? 4 : 0)];
            a   += h * Wv[cc];
            b2s += h * Wv[HH + cc];
        }
        g_sa[r0 + tid] = a;
        g_sb[r0 + tid] = b2s;
    }
}

// ---------------------------------------------------------------------------
// Kernel 2: streaming rel-dot v3 — issue-lean: 4 lanes per pair, 16B/lane,
// packed f32x2 math, 4 shfl per 4 pairs. Fully coalesced (64B lane groups).
// ---------------------------------------------------------------------------
#define RD_THREADS 256
#define RD_BLOCKS  2048

__global__ void __launch_bounds__(RD_THREADS)
reldot_kernel(const float* __restrict__ rel, const float* __restrict__ W)
{
    __shared__ float sWv[RR];
    const int tid = threadIdx.x;
    if (tid < RR) sWv[tid] = W[2 * HH + tid];
    __syncthreads();

    const int lane = tid & 31;
    const int qv   = lane & 3;                  // 16-float quarter of the row
    const int lg   = lane >> 2;                 // pair subgroup 0..7
    const int warp = tid >> 5;

    // preload this lane's quarter of Wv into registers (8 f32x2)
    ulonglong2 wv0 = *(const ulonglong2*)&sWv[qv * 16 + 0];
    ulonglong2 wv1 = *(const ulonglong2*)&sWv[qv * 16 + 4];
    ulonglong2 wv2 = *(const ulonglong2*)&sWv[qv * 16 + 8];
    ulonglong2 wv3 = *(const ulonglong2*)&sWv[qv * 16 + 12];

    const size_t stride = (size_t)RD_BLOCKS * 64;   // pairs per grid iteration

    for (size_t p = (size_t)blockIdx.x * 64 + warp * 8 + lg;
         p < (size_t)NN * NN; p += stride) {
        const ulonglong2* rp = (const ulonglong2*)(rel + p * RR + (size_t)qv * 16);
        ulonglong2 d0 = rp[0], d1 = rp[1], d2 = rp[2], d3 = rp[3];

        u64 dacc = 0, sacc = 0;
        dacc = ffma2(d0.x, wv0.x, dacc);  sacc = add2(d0.x, sacc);
        dacc = ffma2(d0.y, wv0.y, dacc);  sacc = add2(d0.y, sacc);
        dacc = ffma2(d1.x, wv1.x, dacc);  sacc = add2(d1.x, sacc);
        dacc = ffma2(d1.y, wv1.y, dacc);  sacc = add2(d1.y, sacc);
        dacc = ffma2(d2.x, wv2.x, dacc);  sacc = add2(d2.x, sacc);
        dacc = ffma2(d2.y, wv2.y, dacc);  sacc = add2(d2.y, sacc);
        dacc = ffma2(d3.x, wv3.x, dacc);  sacc = add2(d3.x, sacc);
        dacc = ffma2(d3.y, wv3.y, dacc);  sacc = add2(d3.y, sacc);

        float dot  = hsum2(dacc);
        float ssum = hsum2(sacc);
        dot  += __shfl_xor_sync(0xffffffffu, dot, 1);
        ssum += __shfl_xor_sync(0xffffffffu, ssum, 1);
        dot  += __shfl_xor_sync(0xffffffffu, dot, 2);
        ssum += __shfl_xor_sync(0xffffffffu, ssum, 2);
        if (qv == 0) {
            g_dot[p] = dot;
            g_sum[p] = ssum;
        }
    }
}

// ---------------------------------------------------------------------------
// Kernel 3: softmax + agg + FC v5 — double-buffered tile pipeline (R16).
// ---------------------------------------------------------------------------
#define A5_THREADS 512
#define TLD 72

__global__ void __launch_bounds__(A5_THREADS)
att5_kernel(const float* __restrict__ bsc,
            const float* __restrict__ fc_w,
            const float* __restrict__ fc_b,
            float* __restrict__ out)
{
    __shared__ float sP[8 * NN];
    __shared__ float sT[2][64 * TLD];
    __shared__ float sWmax[16];
    __shared__ float sWsum[16];
    __shared__ float sDen[8];
    __shared__ float sRed[16];

    const int tid  = threadIdx.x;
    const int wid  = tid >> 5;
    const int lane = tid & 31;
    const int i0   = blockIdx.x * 8;

    const int r    = wid >> 1;
    const int part = ((wid & 1) << 5) + lane;
    const int i    = i0 + r;
    const float sa_i = g_sa[i];
    const float bval = bsc[0];

    float tv[16];
    float mx = -INFINITY;
    #pragma unroll
    for (int q4 = 0; q4 < 4; q4++) {
        int j = part * 16 + q4 * 4;
        float4 d4 = *(const float4*)&g_dot[(size_t)i * NN + j];
        float4 s4 = *(const float4*)&g_sum[(size_t)i * NN + j];
        #pragma unroll
        for (int e = 0; e < 4; e++) {
            float dot  = (&d4.x)[e];
            float ssum = (&s4.x)[e];
            float w = sa_i + g_sb[j + e] + dot + bval;
            w = (w >= 0.f) ? w : SLOPE * w;
            float m  = (ssum != 0.f) ? 1.f : 0.f;
            float t  = m * w;
            if (t == 0.f) t = NEG_VAL;
            tv[q4 * 4 + e] = t;
            sP[r * NN + j + e] = m;
            mx = fmaxf(mx, t);
        }
    }
    #pragma unroll
    for (int off = 16; off; off >>= 1) mx = fmaxf(mx, __shfl_xor_sync(0xffffffffu, mx, off));
    if (lane == 0) sWmax[wid] = mx;
    __syncthreads();
    mx = fmaxf(sWmax[r * 2], sWmax[r * 2 + 1]);

    float lsum = 0.f;
    #pragma unroll
    for (int q = 0; q < 16; q++) {
        int j = part * 16 + q;
        float e = __expf(tv[q] - mx);
        lsum += e;
        sP[r * NN + j] = e * sP[r * NN + j];
    }
    #pragma unroll
    for (int off = 16; off; off >>= 1) lsum += __shfl_xor_sync(0xffffffffu, lsum, off);
    if (lane == 0) sWsum[wid] = lsum;
    __syncthreads();
    if (tid < 8) sDen[tid] = sWsum[tid * 2] + sWsum[tid * 2 + 1];

    const int js  = tid & 3;
    const int cg  = (tid >> 2) & 15;
    const int rr2 = tid >> 6;
    const int fr0 = tid >> 4, fc0 = (tid & 15) * 4;
    const int fr1 = (tid + A5_THREADS) >> 4;

    float4 pf0 = *(const float4*)&g_h1[(size_t)tid * 4];
    float4 pf1 = *(const float4*)&g_h1[(size_t)(tid + A5_THREADS) * 4];
    *(float4*)&sT[0][fr0 * TLD + fc0] = pf0;
    *(float4*)&sT[0][fr1 * TLD + fc0] = pf1;
    __syncthreads();

    u64 a0 = 0, a1 = 0;
    for (int tile = 0; tile < 16; tile++) {
        const int cur = tile & 1, nxt = cur ^ 1;

        if (tile < 15) {
            pf0 = *(const float4*)&g_h1[(size_t)(tile + 1) * 4096 + (size_t)tid * 4];
            pf1 = *(const float4*)&g_h1[(size_t)(tile + 1) * 4096 + (size_t)(tid + A5_THREADS) * 4];
        }

        const float* pr = &sP[rr2 * NN + tile * 64];
        const float* tb = sT[cur];
        #pragma unroll
        for (int jj = 0; jj < 16; jj++) {
            int jl = jj * 4 + js;
            float p = pr[jl];
            u64 pp;
            asm("mov.b64 %0, {%1, %1};" : "=l"(pp) : "f"(p));
            ulonglong2 tvv = *(const ulonglong2*)&tb[jl * TLD + cg * 4];
            a0 = ffma2(pp, tvv.x, a0);
            a1 = ffma2(pp, tvv.y, a1);
        }

        if (tile < 15) {
            *(float4*)&sT[nxt][fr0 * TLD + fc0] = pf0;
            *(float4*)&sT[nxt][fr1 * TLD + fc0] = pf1;
            __syncthreads();
        }
    }

    float acc;
    {
        float v0, v1, v2, v3;
        asm("mov.b64 {%0,%1}, %2;" : "=f"(v0), "=f"(v1) : "l"(a0));
        asm("mov.b64 {%0,%1}, %2;" : "=f"(v2), "=f"(v3) : "l"(a1));
        const bool hiA = (js & 1);
        const bool hiB = ((js >> 1) & 1);
        float t0 = __shfl_xor_sync(0xffffffffu, hiA ? v0 : v2, 1);
        float t1 = __shfl_xor_sync(0xffffffffu, hiA ? v1 : v3, 1);
        float va = (hiA ? v2 : v0) + t0;
        float vb = (hiA ? v3 : v1) + t1;
        float t2 = __shfl_xor_sync(0xffffffffu, hiB ? va : vb, 2);
        acc = (hiB ? vb : va) + t2;
    }
    const int c_own = cg * 4 + (js & 1) * 2 + (js >> 1);

    const float inv = 1.0f / sDen[rr2];
    float val = g_h1[(size_t)(i0 + rr2) * HH + c_own] * fc_w[c_own]
              + acc * inv * fc_w[HH + c_own];
    #pragma unroll
    for (int off = 16; off; off >>= 1) val += __shfl_xor_sync(0xffffffffu, val, off);
    if (lane == 0) sRed[wid] = val;
    __syncthreads();
    if (tid < 8)
        out[i0 + tid] = sRed[tid * 2] + sRed[tid * 2 + 1] + fc_b[0];
}

// ---------------------------------------------------------------------------
// Launch: gru first on main stream, reldot forked alongside it.
// ---------------------------------------------------------------------------
extern "C" void kernel_launch(void* const* d_in, const int* in_sizes, int n_in,
                              void* d_out, int out_size)
{
    const float* x    = (const float*)d_in[0];
    const float* rel  = (const float*)d_in[1];
    const float* W    = (const float*)d_in[2];
    const float* b    = (const float*)d_in[3];
    const float* fc_w = (const float*)d_in[4];
    const float* fc_b = (const float*)d_in[5];
    const float* Wih0 = (const float*)d_in[6];
    const float* Whh0 = (const float*)d_in[7];
    const float* bih0 = (const float*)d_in[8];
    const float* bhh0 = (const float*)d_in[9];
    const float* Wih1 = (const float*)d_in[10];
    const float* Whh1 = (const float*)d_in[11];
    const float* bih1 = (const float*)d_in[12];
    const float* bhh1 = (const float*)d_in[13];
    float* out = (float*)d_out;

    const size_t gru_smem =
        (3 * GG * W2 + GG * 8 + GRU_ROWS * 360 + 2 * 64 +
         4 * GRU_ROWS * H2) * sizeof(float);
    cudaFuncSetAttribute(gru_kernel, cudaFuncAttributeMaxDynamicSharedMemorySize,
                         (int)gru_smem);

    cudaStream_t s1;
    cudaEvent_t eFork, eJoin;
    cudaStreamCreateWithFlags(&s1, cudaStreamNonBlocking);
    cudaEventCreateWithFlags(&eFork, cudaEventDisableTiming);
    cudaEventCreateWithFlags(&eJoin, cudaEventDisableTiming);

    cudaEventRecord(eFork, 0);
    cudaStreamWaitEvent(s1, eFork, 0);

    gru_kernel<<<NN / GRU_ROWS, GRU_THREADS, gru_smem>>>(
        x, Wih0, Whh0, bih0, bhh0, Wih1, Whh1, bih1, bhh1, W);

    reldot_kernel<<<RD_BLOCKS, RD_THREADS, 0, s1>>>(rel, W);
    cudaEventRecord(eJoin, s1);

    cudaStreamWaitEvent(0, eJoin, 0);

    att5_kernel<<<NN / 8, A5_THREADS>>>(b, fc_w, fc_b, out);
}